// round 2
// baseline (speedup 1.0000x reference)
#include <cuda_runtime.h>
#include <math.h>

// ---------------------------------------------------------------------------
// ReplacementPolicyHead — Round 1 baseline (fp32 SIMT, packed f32x2 FMA)
//
// Pipeline:
//   A) g_H  = mish(x @ W1 + b1)        M=131072, N=768, K=768
//   B) g_QK = h @ [Wq | Wk] + [bq|bk]  M=131072, N=128, K=768
//   C) per-batch: scores = q k^T * 0.125, promotion head, gather by indices
// Scratch via __device__ globals (no allocations, graph-capturable).
// ---------------------------------------------------------------------------

#define B_BATCH   2048
#define SEQ       64
#define DMODEL    768
#define DPOL      64
#define M_ROWS    (B_BATCH * SEQ)        // 131072

__device__ float g_H [M_ROWS * DMODEL];  // 402 MB scratch
__device__ float g_QK[M_ROWS * 128];     // 67 MB scratch (q cols 0..63, k cols 64..127)

// ---- packed f32x2 helpers --------------------------------------------------
__device__ __forceinline__ unsigned long long pack2(float x, float y) {
    unsigned long long r;
    asm("mov.b64 %0, {%1, %2};" : "=l"(r) : "f"(x), "f"(y));
    return r;
}
__device__ __forceinline__ void ffma2(unsigned long long& d,
                                      unsigned long long a,
                                      unsigned long long b) {
    asm("fma.rn.f32x2 %0, %1, %2, %0;" : "+l"(d) : "l"(a), "l"(b));
}
__device__ __forceinline__ float2 unpack2(unsigned long long v) {
    float2 r;
    asm("mov.b64 {%0, %1}, %2;" : "=f"(r.x), "=f"(r.y) : "l"(v));
    return r;
}

__device__ __forceinline__ float mish_f(float c) {
    float sp = (c > 15.0f) ? c : log1pf(expf(c));
    return c * tanhf(sp);
}

// ---------------------------------------------------------------------------
// Kernel A: H = mish(X @ W1 + b1).  128x128 CTA tile, K-chunk 8,
// per-thread 8x8 via packed f32x2 accumulators.
// grid = (M/128, 768/128), block = 256
// ---------------------------------------------------------------------------
__global__ __launch_bounds__(256) void k_gemm_mish(
    const float* __restrict__ X, const float* __restrict__ W1,
    const float* __restrict__ b1)
{
    __shared__ float As[8][128];
    __shared__ float Bs[8][128];

    const int tid = threadIdx.x;
    const int tx  = tid & 15;          // 0..15 -> col group
    const int ty  = tid >> 4;          // 0..15 -> row group
    const int m0  = blockIdx.x * 128;
    const int n0  = blockIdx.y * 128;

    // loader indices
    const int a_row = tid >> 1;            // 0..127
    const int a_kk  = (tid & 1) * 4;       // 0 or 4
    const int b_kk  = tid >> 5;            // 0..7
    const int b_col = (tid & 31) * 4;      // 0..124

    unsigned long long acc[8][4];
#pragma unroll
    for (int i = 0; i < 8; i++)
#pragma unroll
        for (int j = 0; j < 4; j++) acc[i][j] = 0ULL;   // {0.f,0.f}

    for (int k0 = 0; k0 < DMODEL; k0 += 8) {
        float4 av = *(const float4*)&X[(size_t)(m0 + a_row) * DMODEL + k0 + a_kk];
        As[a_kk + 0][a_row] = av.x;
        As[a_kk + 1][a_row] = av.y;
        As[a_kk + 2][a_row] = av.z;
        As[a_kk + 3][a_row] = av.w;
        float4 bv = *(const float4*)&W1[(size_t)(k0 + b_kk) * DMODEL + n0 + b_col];
        *(float4*)&Bs[b_kk][b_col] = bv;
        __syncthreads();

#pragma unroll
        for (int kk = 0; kk < 8; kk++) {
            float4 a0 = *(const float4*)&As[kk][ty * 8];
            float4 a1 = *(const float4*)&As[kk][ty * 8 + 4];
            ulonglong2 bA = *(const ulonglong2*)&Bs[kk][tx * 8];
            ulonglong2 bB = *(const ulonglong2*)&Bs[kk][tx * 8 + 4];
            unsigned long long bb[4] = {bA.x, bA.y, bB.x, bB.y};
            float a[8] = {a0.x, a0.y, a0.z, a0.w, a1.x, a1.y, a1.z, a1.w};
#pragma unroll
            for (int ii = 0; ii < 8; ii++) {
                unsigned long long aa = pack2(a[ii], a[ii]);
#pragma unroll
                for (int j2 = 0; j2 < 4; j2++) ffma2(acc[ii][j2], aa, bb[j2]);
            }
        }
        __syncthreads();
    }

#pragma unroll
    for (int ii = 0; ii < 8; ii++) {
        int row = m0 + ty * 8 + ii;
#pragma unroll
        for (int j2 = 0; j2 < 4; j2++) {
            float2 v = unpack2(acc[ii][j2]);
            int n = n0 + tx * 8 + j2 * 2;
            float c0 = v.x + b1[n];
            float c1 = v.y + b1[n + 1];
            g_H[(size_t)row * DMODEL + n]     = mish_f(c0);
            g_H[(size_t)row * DMODEL + n + 1] = mish_f(c1);
        }
    }
}

// ---------------------------------------------------------------------------
// Kernel B: QK = H @ [Wq | Wk] + [bq | bk].  N = 128 (single col tile).
// grid = M/128, block = 256
// ---------------------------------------------------------------------------
__global__ __launch_bounds__(256) void k_gemm_qk(
    const float* __restrict__ Wq, const float* __restrict__ bq,
    const float* __restrict__ Wk, const float* __restrict__ bk)
{
    __shared__ float As[8][128];
    __shared__ float Bs[8][128];

    const int tid = threadIdx.x;
    const int tx  = tid & 15;
    const int ty  = tid >> 4;
    const int m0  = blockIdx.x * 128;

    const int a_row = tid >> 1;
    const int a_kk  = (tid & 1) * 4;
    const int b_kk  = tid >> 5;
    const int b_col = (tid & 31) * 4;

    unsigned long long acc[8][4];
#pragma unroll
    for (int i = 0; i < 8; i++)
#pragma unroll
        for (int j = 0; j < 4; j++) acc[i][j] = 0ULL;

    for (int k0 = 0; k0 < DMODEL; k0 += 8) {
        float4 av = *(const float4*)&g_H[(size_t)(m0 + a_row) * DMODEL + k0 + a_kk];
        As[a_kk + 0][a_row] = av.x;
        As[a_kk + 1][a_row] = av.y;
        As[a_kk + 2][a_row] = av.z;
        As[a_kk + 3][a_row] = av.w;
        const float* src = (b_col < 64)
            ? &Wq[(size_t)(k0 + b_kk) * DPOL + b_col]
            : &Wk[(size_t)(k0 + b_kk) * DPOL + (b_col - 64)];
        *(float4*)&Bs[b_kk][b_col] = *(const float4*)src;
        __syncthreads();

#pragma unroll
        for (int kk = 0; kk < 8; kk++) {
            float4 a0 = *(const float4*)&As[kk][ty * 8];
            float4 a1 = *(const float4*)&As[kk][ty * 8 + 4];
            ulonglong2 bA = *(const ulonglong2*)&Bs[kk][tx * 8];
            ulonglong2 bB = *(const ulonglong2*)&Bs[kk][tx * 8 + 4];
            unsigned long long bb[4] = {bA.x, bA.y, bB.x, bB.y};
            float a[8] = {a0.x, a0.y, a0.z, a0.w, a1.x, a1.y, a1.z, a1.w};
#pragma unroll
            for (int ii = 0; ii < 8; ii++) {
                unsigned long long aa = pack2(a[ii], a[ii]);
#pragma unroll
                for (int j2 = 0; j2 < 4; j2++) ffma2(acc[ii][j2], aa, bb[j2]);
            }
        }
        __syncthreads();
    }

#pragma unroll
    for (int ii = 0; ii < 8; ii++) {
        int row = m0 + ty * 8 + ii;
#pragma unroll
        for (int j2 = 0; j2 < 4; j2++) {
            float2 v = unpack2(acc[ii][j2]);
            int n = tx * 8 + j2 * 2;
            float bias0 = (n     < 64) ? bq[n]     : bk[n - 64];
            float bias1 = (n + 1 < 64) ? bq[n + 1] : bk[n + 1 - 64];
            g_QK[(size_t)row * 128 + n]     = v.x + bias0;
            g_QK[(size_t)row * 128 + n + 1] = v.y + bias1;
        }
    }
}

// ---------------------------------------------------------------------------
// Kernel C: per-batch scores + promotion + gather.
// grid = B, block = 256
// policy[0..4095]  = scores[i][j]              (i = idx/64, j = idx%64)
// policy[4096+p]   = scores[48+(p/3)/8][56+(p/3)%8] + prom2[p%24]
//   prom2[m] = k[56+m/3] . (Wp[:,m%3] + Wp[:,3]) + bp[m%3] + bp[3]
// ---------------------------------------------------------------------------
__global__ __launch_bounds__(256) void k_scores_gather(
    const float* __restrict__ Wp, const float* __restrict__ bp,
    const int* __restrict__ indices, float* __restrict__ out)
{
    __shared__ float q_s[64][65];
    __shared__ float k_s[64][65];
    __shared__ float s_s[64][64];
    __shared__ float prom2[24];

    const int b   = blockIdx.x;
    const int tid = threadIdx.x;

    for (int i = tid; i < 64 * 64; i += 256) {
        int r = i >> 6, c = i & 63;
        const float* row = &g_QK[((size_t)b * 64 + r) * 128];
        q_s[r][c] = row[c];
        k_s[r][c] = row[64 + c];
    }
    __syncthreads();

    for (int t = tid; t < 4096; t += 256) {
        int i = t >> 6, j = t & 63;
        float acc = 0.0f;
#pragma unroll
        for (int d = 0; d < 64; d++) acc += q_s[i][d] * k_s[j][d];
        s_s[i][j] = acc * 0.125f;
    }

    if (tid < 24) {
        int jr = 56 + tid / 3;
        int c  = tid % 3;
        float acc = bp[c] + bp[3];
#pragma unroll
        for (int d = 0; d < 64; d++)
            acc += k_s[jr][d] * (Wp[d * 4 + c] + Wp[d * 4 + 3]);
        prom2[tid] = acc;
    }
    __syncthreads();

    for (int t = tid; t < 1858; t += 256) {
        int id = indices[t];
        float v;
        if (id < 4096) {
            v = s_s[id >> 6][id & 63];
        } else {
            int p = id - 4096;
            int i = p / 3;
            v = s_s[48 + (i >> 3)][56 + (i & 7)] + prom2[p % 24];
        }
        out[(size_t)b * 1858 + t] = v;
    }
}

// ---------------------------------------------------------------------------
extern "C" void kernel_launch(void* const* d_in, const int* in_sizes, int n_in,
                              void* d_out, int out_size)
{
    const float* x   = (const float*)d_in[0];
    const float* W1  = (const float*)d_in[1];
    const float* b1  = (const float*)d_in[2];
    const float* Wq  = (const float*)d_in[3];
    const float* bq  = (const float*)d_in[4];
    const float* Wk  = (const float*)d_in[5];
    const float* bk  = (const float*)d_in[6];
    const float* Wp  = (const float*)d_in[7];
    const float* bp  = (const float*)d_in[8];
    const int*   idx = (const int*)d_in[9];

    dim3 gA(M_ROWS / 128, DMODEL / 128);   // (1024, 6)
    k_gemm_mish<<<gA, 256>>>(x, W1, b1);

    k_gemm_qk<<<M_ROWS / 128, 256>>>(Wq, bq, Wk, bk);

    k_scores_gather<<<B_BATCH, 256>>>(Wp, bp, idx, (float*)d_out);
}